// round 10
// baseline (speedup 1.0000x reference)
#include <cuda_runtime.h>
#include <cuda_fp16.h>
#include <cstdint>
#include <cstddef>
#include <cmath>

// Problem constants
#define T_STEPS 1000
#define BATCH   64
#define NDIM    512
#define KDIM    512
#define MROWS   (BATCH * T_STEPS)   // 64000

#define NCHUNKS   4
#define B_PER_CHK (BATCH / NCHUNKS)            // 16 batches per chunk
#define ROWS_CHK  (B_PER_CHK * T_STEPS)        // 16000 rows per chunk

static constexpr size_t PLANE      = (size_t)BATCH * NDIM;          // 32768
static constexpr size_t STATES_OFF = (size_t)T_STEPS * PLANE;       // outputs plane elems
static constexpr size_t DEC_OFF    = STATES_OFF + 3 * STATES_OFF;   // after states [T,3,B,N]

// Scratch
__device__ __align__(16) float g_I[(size_t)MROWS * NDIM];
__device__ float g_r[T_STEPS * BATCH];

// ---------------------------------------------------------------------------
// fp16 Dekker-pair: x -> half2(hi=rn16(x), lo=rn16(x-hi)), interleaved along
// mma-k. pass1 (A x B) = hi*hi + lo*lo; pass2 (A x swap16(B)) = hi*lo + lo*hi.
// ---------------------------------------------------------------------------
__device__ __forceinline__ uint32_t pack_hilo(float x) {
    __half h = __float2half_rn(x);
    float r = x - __half2float(h);
    __half2 p = __halves2half2(h, __float2half_rn(r));
    return *reinterpret_cast<uint32_t*>(&p);
}

__device__ __forceinline__ void mma_f16(float* c, const uint32_t* a, const uint32_t* b) {
    asm volatile(
        "mma.sync.aligned.m16n8k16.row.col.f32.f16.f16.f32 "
        "{%0,%1,%2,%3}, {%4,%5,%6,%7}, {%8,%9}, {%0,%1,%2,%3};\n"
        : "+f"(c[0]), "+f"(c[1]), "+f"(c[2]), "+f"(c[3])
        : "r"(a[0]), "r"(a[1]), "r"(a[2]), "r"(a[3]), "r"(b[0]), "r"(b[1]));
}

__device__ __forceinline__ void ldsm_x4(uint32_t* r, uint32_t saddr) {
    asm volatile("ldmatrix.sync.aligned.m8n8.x4.shared.b16 {%0,%1,%2,%3}, [%4];"
                 : "=r"(r[0]), "=r"(r[1]), "=r"(r[2]), "=r"(r[3]) : "r"(saddr));
}

// ---------------------------------------------------------------------------
// Kernel 1: I = X @ W1^T (NT GEMM) — R9-exact compute, bm_base chunk offset.
// ---------------------------------------------------------------------------
#define BKR    32
#define GCHUNK (KDIM / BKR)        // 16 k-chunks
#define WSTR   36
#define TILEW  (128 * WSTR)
#define STAGEW (2 * TILEW)

struct LdgRegs { float4 a[2]; float4 b[2]; };

__device__ __forceinline__ void ldg_chunk(LdgRegs& r, const float* __restrict__ xptr,
                                          const float* __restrict__ wptr, int ck)
{
    const float4* xa = (const float4*)(xptr + ck * BKR);
    const float4* wa = (const float4*)(wptr + ck * BKR);
    r.a[0] = xa[0]; r.a[1] = xa[1];
    r.b[0] = wa[0]; r.b[1] = wa[1];
}

__device__ __forceinline__ void sts_chunk(uint32_t* stage, const LdgRegs& r, int row, int kb)
{
    uint32_t* sA = stage + row * WSTR + kb;
    uint32_t* sB = sA + TILEW;
    const float* fa = (const float*)r.a;
    const float* fb = (const float*)r.b;
    #pragma unroll
    for (int j = 0; j < 2; j++) {
        uint4 w;
        w.x = pack_hilo(fa[j * 4 + 0]); w.y = pack_hilo(fa[j * 4 + 1]);
        w.z = pack_hilo(fa[j * 4 + 2]); w.w = pack_hilo(fa[j * 4 + 3]);
        ((uint4*)sA)[j] = w;
    }
    #pragma unroll
    for (int j = 0; j < 2; j++) {
        uint4 w;
        w.x = pack_hilo(fb[j * 4 + 0]); w.y = pack_hilo(fb[j * 4 + 1]);
        w.z = pack_hilo(fb[j * 4 + 2]); w.w = pack_hilo(fb[j * 4 + 3]);
        ((uint4*)sB)[j] = w;
    }
}

__device__ __forceinline__ void compute_chunk(uint32_t stage_saddr,
                                              float (&acc)[2][4][4],
                                              uint32_t aOff, uint32_t bOff)
{
    #pragma unroll
    for (int s = 0; s < 4; s++) {
        const uint32_t kByte = (uint32_t)(s * 8) * 4u;
        uint32_t A[2][4];
        ldsm_x4(A[0], stage_saddr + aOff + kByte);
        ldsm_x4(A[1], stage_saddr + aOff + (uint32_t)(16 * WSTR * 4) + kByte);
        uint32_t Bt[2][4];
        ldsm_x4(Bt[0], stage_saddr + bOff + kByte);
        ldsm_x4(Bt[1], stage_saddr + bOff + (uint32_t)(16 * WSTR * 4) + kByte);

        #pragma unroll
        for (int mt = 0; mt < 2; mt++)
            #pragma unroll
            for (int nt = 0; nt < 4; nt++)
                mma_f16(acc[mt][nt], A[mt], &Bt[nt >> 1][(nt & 1) * 2]);
        #pragma unroll
        for (int nt = 0; nt < 4; nt++) {
            uint32_t bs[2];
            bs[0] = __byte_perm(Bt[nt >> 1][(nt & 1) * 2 + 0], 0, 0x1032);
            bs[1] = __byte_perm(Bt[nt >> 1][(nt & 1) * 2 + 1], 0, 0x1032);
            #pragma unroll
            for (int mt = 0; mt < 2; mt++)
                mma_f16(acc[mt][nt], A[mt], bs);
        }
    }
}

__global__ __launch_bounds__(512, 1) void gemm_f16pair_kernel(const float* __restrict__ X,
                                                              const float* __restrict__ W,
                                                              int bm_base)
{
    extern __shared__ uint32_t smemw[];
    const int tid  = threadIdx.x;
    const int wid  = tid >> 5;
    const int lane = tid & 31;
    const int wm   = wid & 3;
    const int wn   = wid >> 2;
    const int bm   = bm_base + blockIdx.x * 128;
    const int bn   = blockIdx.y * 128;

    const uint32_t smem_saddr = (uint32_t)__cvta_generic_to_shared(smemw);

    const int lm = lane & 7;
    const int aRow = wm * 32 + lm + ((lane >> 3) & 1) * 8;
    const int aWrd = ((lane >> 4) & 1) * 4;
    const uint32_t aOff = (uint32_t)(aRow * WSTR + aWrd) * 4u;
    const int bRow = wn * 32 + lm + ((lane >> 4) & 1) * 8;
    const int bWrd = ((lane >> 3) & 1) * 4;
    const uint32_t bOff = (uint32_t)(TILEW + bRow * WSTR + bWrd) * 4u;

    const int lrow = tid >> 2;
    const int lkb  = (tid & 3) * 8;
    const float* xptr = X + (size_t)(bm + lrow) * KDIM + lkb;
    const float* wptr = W + (size_t)(bn + lrow) * KDIM + lkb;

    float acc[2][4][4];
    #pragma unroll
    for (int mt = 0; mt < 2; mt++)
        #pragma unroll
        for (int nt = 0; nt < 4; nt++)
            #pragma unroll
            for (int j = 0; j < 4; j++) acc[mt][nt][j] = 0.f;

    {
        LdgRegs r0;
        ldg_chunk(r0, xptr, wptr, 0);
        sts_chunk(smemw, r0, lrow, lkb);
    }
    __syncthreads();

    #pragma unroll 1
    for (int ck = 0; ck < GCHUNK; ck++) {
        const int cur = ck & 1;
        LdgRegs nr;
        if (ck < GCHUNK - 1) ldg_chunk(nr, xptr, wptr, ck + 1);
        compute_chunk(smem_saddr + (uint32_t)(cur * STAGEW) * 4u, acc, aOff, bOff);
        if (ck < GCHUNK - 1) sts_chunk(smemw + (cur ^ 1) * STAGEW, nr, lrow, lkb);
        __syncthreads();
    }

    #pragma unroll
    for (int mt = 0; mt < 2; mt++) {
        const int r0 = bm + wm * 32 + mt * 16 + (lane >> 2);
        #pragma unroll
        for (int nt = 0; nt < 4; nt++) {
            const int c = bn + wn * 32 + nt * 8 + 2 * (lane & 3);
            *(float2*)(g_I + (size_t)r0 * NDIM + c)       = make_float2(acc[mt][nt][0], acc[mt][nt][1]);
            *(float2*)(g_I + (size_t)(r0 + 8) * NDIM + c) = make_float2(acc[mt][nt][2], acc[mt][nt][3]);
        }
    }
}

// ---------------------------------------------------------------------------
// Kernel 2: per-neuron Izhikevich scan — R9-exact, g_base chunk offset.
// ---------------------------------------------------------------------------
struct NeuronP { float TS, V2, V1, V0, KA, Bp, TH, Cc, D; };

__device__ __forceinline__ void snn_step(float Ic, int t, int g,
                                         const NeuronP& P, float& u, float& v,
                                         float* __restrict__ out)
{
    float t0 = P.V0 - u + Ic;
    t0 = fmaf(P.V1, v, t0);
    t0 = fmaf(P.V2, v * v, t0);
    const float vn = fmaf(P.TS, t0, v);
    const float un = fmaf(P.KA, fmaf(P.Bp, v, -u), u);
    const bool  sp = (vn - P.TH) > 0.f;
    const float s  = sp ? 1.f : 0.f;
    const float vo = sp ? P.Cc : vn;
    const float uo = sp ? (un + P.D) : un;

    out[(size_t)t * PLANE + g] = s;
    const size_t sb = STATES_OFF + (size_t)t * (3 * PLANE) + g;
    out[sb]             = uo;
    out[sb + PLANE]     = vo;
    out[sb + 2 * PLANE] = s;
    u = uo; v = vo;
}

__global__ __launch_bounds__(128) void scan_kernel(
    const float* __restrict__ st,
    const float* __restrict__ pa,  const float* __restrict__ pb,
    const float* __restrict__ pc,  const float* __restrict__ pd,
    const float* __restrict__ pv2, const float* __restrict__ pv1,
    const float* __restrict__ pv0, const float* __restrict__ ptau,
    const float* __restrict__ pth, const float* __restrict__ pts,
    float* __restrict__ out, int g_base)
{
    const int g = g_base + blockIdx.x * 128 + threadIdx.x;
    const int n = g & (NDIM - 1);

    NeuronP P;
    P.TS = pts[n];
    P.V2 = pv2[n]; P.V1 = pv1[n]; P.V0 = pv0[n];
    P.KA = P.TS / ptau[n] * pa[n];
    P.Bp = pb[n]; P.TH = pth[n]; P.Cc = pc[n]; P.D = pd[n];

    float u = st[g];
    float v = st[PLANE + g];

    const float* Ip = g_I + (size_t)(g >> 9) * ((size_t)T_STEPS * NDIM) + n;

    float bufA[8], bufB[8];
    #pragma unroll
    for (int p = 0; p < 8; p++) bufA[p] = Ip[(size_t)p * NDIM];

    #pragma unroll 1
    for (int t0 = 0; t0 < 992; t0 += 16) {
        #pragma unroll
        for (int p = 0; p < 8; p++) bufB[p] = Ip[(size_t)(t0 + 8 + p) * NDIM];
        #pragma unroll
        for (int p = 0; p < 8; p++) snn_step(bufA[p], t0 + p, g, P, u, v, out);
        #pragma unroll
        for (int p = 0; p < 8; p++) bufA[p] = Ip[(size_t)(t0 + 16 + p) * NDIM];
        #pragma unroll
        for (int p = 0; p < 8; p++) snn_step(bufB[p], t0 + 8 + p, g, P, u, v, out);
    }
    #pragma unroll
    for (int p = 0; p < 8; p++) snn_step(bufA[p], 992 + p, g, P, u, v, out);
}

// ---------------------------------------------------------------------------
// Kernel 3: r[t*B+b] = sum_n s[t,b,n] * W2[n] — chunked over b.
// grid (T_STEPS, B_PER_CHK); b = b_base + blockIdx.y
// ---------------------------------------------------------------------------
__global__ __launch_bounds__(128) void readout_reduce_kernel(
    const float* __restrict__ out, const float* __restrict__ W2, int b_base)
{
    const int tb = blockIdx.x * BATCH + (b_base + blockIdx.y);
    const float* sp = out + (size_t)tb * NDIM;
    const int tid = threadIdx.x;

    float sum = 0.f;
    #pragma unroll
    for (int j = 0; j < 4; j++) {
        const int n = tid + j * 128;
        sum = fmaf(sp[n], W2[n], sum);
    }
    #pragma unroll
    for (int o = 16; o > 0; o >>= 1)
        sum += __shfl_xor_sync(0xffffffffu, sum, o);

    __shared__ float ws[4];
    if ((tid & 31) == 0) ws[tid >> 5] = sum;
    __syncthreads();
    if (tid == 0) g_r[tb] = (ws[0] + ws[1]) + (ws[2] + ws[3]);
}

// ---------------------------------------------------------------------------
// Kernel 4: li recurrence (frozen)
// ---------------------------------------------------------------------------
__global__ void li_kernel(const float* __restrict__ stLI,
                          const float* __restrict__ leak,
                          float* __restrict__ out)
{
    const int b = blockIdx.x;
    const int lane = threadIdx.x;
    const float lk = leak[0];
    const float l1 = lk, l2 = l1 * l1, l4 = l2 * l2, l8 = l4 * l4, l16 = l8 * l8;
    float lpow = lk;
    {
        float sq[5] = {l1, l2, l4, l8, l16};
        #pragma unroll
        for (int i = 0; i < 5; i++)
            if ((lane >> i) & 1) lpow *= sq[i];
    }

    float carry = stLI[b];
    float x = g_r[lane * BATCH + b];

    #pragma unroll 1
    for (int t0 = 0; t0 < T_STEPS; t0 += 32) {
        const int tn = t0 + 32 + lane;
        const float xn = (tn < T_STEPS) ? g_r[tn * BATCH + b] : 0.f;

        float y = x, up;
        up = __shfl_up_sync(0xffffffffu, y, 1);  if (lane >= 1)  y = fmaf(l1,  up, y);
        up = __shfl_up_sync(0xffffffffu, y, 2);  if (lane >= 2)  y = fmaf(l2,  up, y);
        up = __shfl_up_sync(0xffffffffu, y, 4);  if (lane >= 4)  y = fmaf(l4,  up, y);
        up = __shfl_up_sync(0xffffffffu, y, 8);  if (lane >= 8)  y = fmaf(l8,  up, y);
        up = __shfl_up_sync(0xffffffffu, y, 16); if (lane >= 16) y = fmaf(l16, up, y);

        const float li = fmaf(lpow, carry, y);
        if (t0 + lane < T_STEPS)
            out[DEC_OFF + (size_t)(t0 + lane) * BATCH + b] = li;
        carry = __shfl_sync(0xffffffffu, li, 31);
        x = xn;
    }
}

// ---------------------------------------------------------------------------
extern "C" void kernel_launch(void* const* d_in, const int* in_sizes, int n_in,
                              void* d_out, int out_size)
{
    const float* x    = (const float*)d_in[0];
    const float* st   = (const float*)d_in[1];
    const float* stLI = (const float*)d_in[2];
    const float* W1   = (const float*)d_in[3];
    const float* W2   = (const float*)d_in[4];
    const float* a_   = (const float*)d_in[5];
    const float* b_   = (const float*)d_in[6];
    const float* c_   = (const float*)d_in[7];
    const float* d_   = (const float*)d_in[8];
    const float* v2_  = (const float*)d_in[9];
    const float* v1_  = (const float*)d_in[10];
    const float* v0_  = (const float*)d_in[11];
    const float* tau_ = (const float*)d_in[12];
    const float* th_  = (const float*)d_in[13];
    const float* lk_  = (const float*)d_in[14];
    const float* ts_  = (const float*)d_in[15];
    float* out = (float*)d_out;

    // One-time side stream + events (created on the uncaptured correctness
    // call; reused identically on every call -> deterministic work).
    static cudaStream_t s_side = nullptr;
    static cudaEvent_t  s_evG[NCHUNKS];
    static cudaEvent_t  s_evJoin = nullptr;
    if (!s_side) {
        cudaStreamCreateWithFlags(&s_side, cudaStreamNonBlocking);
        for (int i = 0; i < NCHUNKS; i++)
            cudaEventCreateWithFlags(&s_evG[i], cudaEventDisableTiming);
        cudaEventCreateWithFlags(&s_evJoin, cudaEventDisableTiming);
    }

    const int smem_bytes = 2 * STAGEW * (int)sizeof(uint32_t);   // 73728
    cudaFuncSetAttribute(gemm_f16pair_kernel,
                         cudaFuncAttributeMaxDynamicSharedMemorySize, smem_bytes);

    // Stream 0: GEMM chunks (16 batches each), event after each.
    dim3 ggrid(ROWS_CHK / 128, NDIM / 128);   // (125, 4)
    for (int c = 0; c < NCHUNKS; c++) {
        gemm_f16pair_kernel<<<ggrid, 512, smem_bytes>>>(x, W1, c * ROWS_CHK);
        cudaEventRecord(s_evG[c], 0);
    }

    // Side stream: scan+reduce for chunk c start as soon as gemm chunk c done,
    // overlapping gemm chunk c+1 on stream 0.
    for (int c = 0; c < NCHUNKS; c++) {
        cudaStreamWaitEvent(s_side, s_evG[c], 0);
        scan_kernel<<<(B_PER_CHK * NDIM) / 128, 128, 0, s_side>>>(
            st, a_, b_, c_, d_, v2_, v1_, v0_, tau_, th_, ts_, out,
            c * B_PER_CHK * NDIM);
        dim3 rgrid(T_STEPS, B_PER_CHK);
        readout_reduce_kernel<<<rgrid, 128, 0, s_side>>>(out, W2, c * B_PER_CHK);
    }

    // Join side stream back into stream 0, then li.
    cudaEventRecord(s_evJoin, s_side);
    cudaStreamWaitEvent(0, s_evJoin, 0);
    li_kernel<<<BATCH, 32>>>(stLI, lk_, out);
}

// round 11
// speedup vs baseline: 1.3136x; 1.3136x over previous
#include <cuda_runtime.h>
#include <cuda_fp16.h>
#include <cstdint>
#include <cstddef>
#include <cmath>

// Problem constants
#define T_STEPS 1000
#define BATCH   64
#define NDIM    512
#define KDIM    512
#define MROWS   (BATCH * T_STEPS)   // 64000

static constexpr size_t PLANE      = (size_t)BATCH * NDIM;          // 32768
static constexpr size_t STATES_OFF = (size_t)T_STEPS * PLANE;       // outputs plane elems
static constexpr size_t DEC_OFF    = STATES_OFF + 3 * STATES_OFF;   // after states [T,3,B,N]

// Scratch
__device__ __align__(16) float g_I[(size_t)MROWS * NDIM];
__device__ float g_r[T_STEPS * BATCH];

// ---------------------------------------------------------------------------
// fp16 Dekker-pair: x -> half2(hi=rn16(x), lo=rn16(x-hi)), interleaved along
// mma-k. pass1 (A x B) = hi*hi + lo*lo; pass2 (swap16(A) x B) = lo*hi + hi*lo.
// Sum = full (hi+lo)(hi+lo) product, ~2^-22 relative error.
// ---------------------------------------------------------------------------
__device__ __forceinline__ uint32_t pack_hilo(float x) {
    __half h = __float2half_rn(x);
    float r = x - __half2float(h);
    __half2 p = __halves2half2(h, __float2half_rn(r));
    return *reinterpret_cast<uint32_t*>(&p);
}

__device__ __forceinline__ void mma_f16(float* c, const uint32_t* a, const uint32_t* b) {
    asm volatile(
        "mma.sync.aligned.m16n8k16.row.col.f32.f16.f16.f32 "
        "{%0,%1,%2,%3}, {%4,%5,%6,%7}, {%8,%9}, {%0,%1,%2,%3};\n"
        : "+f"(c[0]), "+f"(c[1]), "+f"(c[2]), "+f"(c[3])
        : "r"(a[0]), "r"(a[1]), "r"(a[2]), "r"(a[3]), "r"(b[0]), "r"(b[1]));
}

__device__ __forceinline__ void ldsm_x4(uint32_t* r, uint32_t saddr) {
    asm volatile("ldmatrix.sync.aligned.m8n8.x4.shared.b16 {%0,%1,%2,%3}, [%4];"
                 : "=r"(r[0]), "=r"(r[1]), "=r"(r[2]), "=r"(r[3]) : "r"(saddr));
}

// ---------------------------------------------------------------------------
// Kernel 1: I = X @ W1^T (NT GEMM), fp16 Dekker-pair mma, 2 passes.
// R11: 256 threads (8 warps, 4x2), warp tile 32x64, ldmatrix loads,
// __launch_bounds__(256,2) -> 2 CTAs/SM (2x256x128 = 64K regs, 144KB smem).
// Cross-CTA overlap hides barrier + LDSM->mma dependency stalls.
// Pass 2 swaps A (2 LDSM-frag swaps) instead of B (4) -> fewer PRMT.
// smem: stride-36-word rows, 2 stages, 72KB/CTA.
// ---------------------------------------------------------------------------
#define BKR    32
#define GCHUNK (KDIM / BKR)        // 16
#define WSTR   36                  // uint32 words per row (32 data + 4 pad)
#define TILEW  (128 * WSTR)
#define STAGEW (2 * TILEW)

struct LdgRegs { float4 a[4]; float4 b[4]; };   // 16 A floats + 16 B floats

__device__ __forceinline__ void ldg_chunk(LdgRegs& r, const float* __restrict__ xptr,
                                          const float* __restrict__ wptr, int ck)
{
    const float4* xa = (const float4*)(xptr + ck * BKR);
    const float4* wa = (const float4*)(wptr + ck * BKR);
    #pragma unroll
    for (int j = 0; j < 4; j++) r.a[j] = xa[j];
    #pragma unroll
    for (int j = 0; j < 4; j++) r.b[j] = wa[j];
}

__device__ __forceinline__ void sts_chunk(uint32_t* stage, const LdgRegs& r, int row, int kb)
{
    uint32_t* sA = stage + row * WSTR + kb;
    uint32_t* sB = sA + TILEW;
    const float* fa = (const float*)r.a;
    const float* fb = (const float*)r.b;
    #pragma unroll
    for (int j = 0; j < 4; j++) {
        uint4 w;
        w.x = pack_hilo(fa[j * 4 + 0]); w.y = pack_hilo(fa[j * 4 + 1]);
        w.z = pack_hilo(fa[j * 4 + 2]); w.w = pack_hilo(fa[j * 4 + 3]);
        ((uint4*)sA)[j] = w;
    }
    #pragma unroll
    for (int j = 0; j < 4; j++) {
        uint4 w;
        w.x = pack_hilo(fb[j * 4 + 0]); w.y = pack_hilo(fb[j * 4 + 1]);
        w.z = pack_hilo(fb[j * 4 + 2]); w.w = pack_hilo(fb[j * 4 + 3]);
        ((uint4*)sB)[j] = w;
    }
}

__device__ __forceinline__ void compute_chunk(uint32_t stage_saddr,
                                              float (&acc)[2][8][4],
                                              uint32_t aOff, uint32_t bOff)
{
    #pragma unroll
    for (int s = 0; s < 4; s++) {
        const uint32_t kByte = (uint32_t)(s * 8) * 4u;
        uint32_t A[2][4];
        ldsm_x4(A[0], stage_saddr + aOff + kByte);                              // mt 0
        ldsm_x4(A[1], stage_saddr + aOff + (uint32_t)(16 * WSTR * 4) + kByte);  // mt 1
        uint32_t Bt[4][4];                                                      // nt pairs
        #pragma unroll
        for (int p = 0; p < 4; p++)
            ldsm_x4(Bt[p], stage_saddr + bOff + (uint32_t)(p * 16 * WSTR * 4) + kByte);
        // Bt[p] = {nt(2p).b0, nt(2p).b1, nt(2p+1).b0, nt(2p+1).b1}

        // pass 1: hi*hi + lo*lo — distinct accumulators
        #pragma unroll
        for (int mt = 0; mt < 2; mt++)
            #pragma unroll
            for (int nt = 0; nt < 8; nt++)
                mma_f16(acc[mt][nt], A[mt], &Bt[nt >> 1][(nt & 1) * 2]);
        // pass 2: hi*lo + lo*hi — swap A halves (2 frags x 4 regs = 8 PRMT)
        uint32_t As[2][4];
        #pragma unroll
        for (int mt = 0; mt < 2; mt++)
            #pragma unroll
            for (int j = 0; j < 4; j++)
                As[mt][j] = __byte_perm(A[mt][j], 0, 0x1032);
        #pragma unroll
        for (int mt = 0; mt < 2; mt++)
            #pragma unroll
            for (int nt = 0; nt < 8; nt++)
                mma_f16(acc[mt][nt], As[mt], &Bt[nt >> 1][(nt & 1) * 2]);
    }
}

__global__ __launch_bounds__(256, 2) void gemm_f16pair_kernel(const float* __restrict__ X,
                                                              const float* __restrict__ W)
{
    extern __shared__ uint32_t smemw[];      // 2 stages * 9216 words = 72KB
    const int tid  = threadIdx.x;
    const int wid  = tid >> 5;
    const int lane = tid & 31;
    const int wm   = wid & 3;                // 0..3 (M)
    const int wn   = wid >> 2;               // 0..1 (N)
    const int bm   = blockIdx.x * 128;
    const int bn   = blockIdx.y * 128;

    const uint32_t smem_saddr = (uint32_t)__cvta_generic_to_shared(smemw);

    // ldmatrix per-lane offsets (stage-relative, bytes).
    const int lm = lane & 7;
    // A x4: M0=row+0/w0, M1=row+8/w0, M2=row+0/w4, M3=row+8/w4
    const int aRow = wm * 32 + lm + ((lane >> 3) & 1) * 8;
    const int aWrd = ((lane >> 4) & 1) * 4;
    const uint32_t aOff = (uint32_t)(aRow * WSTR + aWrd) * 4u;
    // B x4: M0=row+0/w0, M1=row+0/w4, M2=row+8/w0, M3=row+8/w4
    const int bRow = wn * 64 + lm + ((lane >> 4) & 1) * 8;
    const int bWrd = ((lane >> 3) & 1) * 4;
    const uint32_t bOff = (uint32_t)(TILEW + bRow * WSTR + bWrd) * 4u;

    // loader mapping: row = tid>>1 (0..127), kb = (tid&1)*16 words
    const int lrow = tid >> 1;
    const int lkb  = (tid & 1) * 16;
    const float* xptr = X + (size_t)(bm + lrow) * KDIM + lkb;
    const float* wptr = W + (size_t)(bn + lrow) * KDIM + lkb;

    float acc[2][8][4];
    #pragma unroll
    for (int mt = 0; mt < 2; mt++)
        #pragma unroll
        for (int nt = 0; nt < 8; nt++)
            #pragma unroll
            for (int j = 0; j < 4; j++) acc[mt][nt][j] = 0.f;

    {
        LdgRegs r0;
        ldg_chunk(r0, xptr, wptr, 0);
        sts_chunk(smemw, r0, lrow, lkb);
    }
    __syncthreads();

    #pragma unroll 1
    for (int ck = 0; ck < GCHUNK; ck++) {
        const int cur = ck & 1;
        LdgRegs nr;
        if (ck < GCHUNK - 1) ldg_chunk(nr, xptr, wptr, ck + 1);   // LDGs in flight
        compute_chunk(smem_saddr + (uint32_t)(cur * STAGEW) * 4u, acc, aOff, bOff);
        if (ck < GCHUNK - 1) sts_chunk(smemw + (cur ^ 1) * STAGEW, nr, lrow, lkb);
        __syncthreads();
    }

    // Epilogue: direct float2 stores to g_I
    #pragma unroll
    for (int mt = 0; mt < 2; mt++) {
        const int r0 = bm + wm * 32 + mt * 16 + (lane >> 2);
        #pragma unroll
        for (int nt = 0; nt < 8; nt++) {
            const int c = bn + wn * 64 + nt * 8 + 2 * (lane & 3);
            *(float2*)(g_I + (size_t)r0 * NDIM + c)       = make_float2(acc[mt][nt][0], acc[mt][nt][1]);
            *(float2*)(g_I + (size_t)(r0 + 8) * NDIM + c) = make_float2(acc[mt][nt][2], acc[mt][nt][3]);
        }
    }
}

// ---------------------------------------------------------------------------
// Kernel 2: per-neuron Izhikevich scan (frozen, R9-exact)
// ---------------------------------------------------------------------------
struct NeuronP { float TS, V2, V1, V0, KA, Bp, TH, Cc, D; };

__device__ __forceinline__ void snn_step(float Ic, int t, int g,
                                         const NeuronP& P, float& u, float& v,
                                         float* __restrict__ out)
{
    float t0 = P.V0 - u + Ic;
    t0 = fmaf(P.V1, v, t0);
    t0 = fmaf(P.V2, v * v, t0);
    const float vn = fmaf(P.TS, t0, v);
    const float un = fmaf(P.KA, fmaf(P.Bp, v, -u), u);
    const bool  sp = (vn - P.TH) > 0.f;
    const float s  = sp ? 1.f : 0.f;
    const float vo = sp ? P.Cc : vn;
    const float uo = sp ? (un + P.D) : un;

    out[(size_t)t * PLANE + g] = s;
    const size_t sb = STATES_OFF + (size_t)t * (3 * PLANE) + g;
    out[sb]             = uo;
    out[sb + PLANE]     = vo;
    out[sb + 2 * PLANE] = s;
    u = uo; v = vo;
}

__global__ __launch_bounds__(128) void scan_kernel(
    const float* __restrict__ st,
    const float* __restrict__ pa,  const float* __restrict__ pb,
    const float* __restrict__ pc,  const float* __restrict__ pd,
    const float* __restrict__ pv2, const float* __restrict__ pv1,
    const float* __restrict__ pv0, const float* __restrict__ ptau,
    const float* __restrict__ pth, const float* __restrict__ pts,
    float* __restrict__ out)
{
    const int g = blockIdx.x * 128 + threadIdx.x;
    const int n = g & (NDIM - 1);

    NeuronP P;
    P.TS = pts[n];
    P.V2 = pv2[n]; P.V1 = pv1[n]; P.V0 = pv0[n];
    P.KA = P.TS / ptau[n] * pa[n];
    P.Bp = pb[n]; P.TH = pth[n]; P.Cc = pc[n]; P.D = pd[n];

    float u = st[g];
    float v = st[PLANE + g];

    const float* Ip = g_I + (size_t)(g >> 9) * ((size_t)T_STEPS * NDIM) + n;

    float bufA[8], bufB[8];
    #pragma unroll
    for (int p = 0; p < 8; p++) bufA[p] = Ip[(size_t)p * NDIM];

    #pragma unroll 1
    for (int t0 = 0; t0 < 992; t0 += 16) {
        #pragma unroll
        for (int p = 0; p < 8; p++) bufB[p] = Ip[(size_t)(t0 + 8 + p) * NDIM];
        #pragma unroll
        for (int p = 0; p < 8; p++) snn_step(bufA[p], t0 + p, g, P, u, v, out);
        #pragma unroll
        for (int p = 0; p < 8; p++) bufA[p] = Ip[(size_t)(t0 + 16 + p) * NDIM];
        #pragma unroll
        for (int p = 0; p < 8; p++) snn_step(bufB[p], t0 + 8 + p, g, P, u, v, out);
    }
    #pragma unroll
    for (int p = 0; p < 8; p++) snn_step(bufA[p], 992 + p, g, P, u, v, out);
}

// ---------------------------------------------------------------------------
// Kernel 3: r[t*B+b] = sum_n s[t,b,n] * W2[n]  (frozen)
// ---------------------------------------------------------------------------
__global__ __launch_bounds__(128) void readout_reduce_kernel(
    const float* __restrict__ out, const float* __restrict__ W2)
{
    const int tb = blockIdx.x;
    const float* sp = out + (size_t)tb * NDIM;
    const int tid = threadIdx.x;

    float sum = 0.f;
    #pragma unroll
    for (int j = 0; j < 4; j++) {
        const int n = tid + j * 128;
        sum = fmaf(sp[n], W2[n], sum);
    }
    #pragma unroll
    for (int o = 16; o > 0; o >>= 1)
        sum += __shfl_xor_sync(0xffffffffu, sum, o);

    __shared__ float ws[4];
    if ((tid & 31) == 0) ws[tid >> 5] = sum;
    __syncthreads();
    if (tid == 0) g_r[tb] = (ws[0] + ws[1]) + (ws[2] + ws[3]);
}

// ---------------------------------------------------------------------------
// Kernel 4: li recurrence — warp-parallel linear-recurrence scan (frozen)
// ---------------------------------------------------------------------------
__global__ void li_kernel(const float* __restrict__ stLI,
                          const float* __restrict__ leak,
                          float* __restrict__ out)
{
    const int b = blockIdx.x;
    const int lane = threadIdx.x;    // 32 threads
    const float lk = leak[0];
    const float l1 = lk, l2 = l1 * l1, l4 = l2 * l2, l8 = l4 * l4, l16 = l8 * l8;
    float lpow = lk;                 // leak^(lane+1)
    {
        float sq[5] = {l1, l2, l4, l8, l16};
        #pragma unroll
        for (int i = 0; i < 5; i++)
            if ((lane >> i) & 1) lpow *= sq[i];
    }

    float carry = stLI[b];
    float x = g_r[lane * BATCH + b];

    #pragma unroll 1
    for (int t0 = 0; t0 < T_STEPS; t0 += 32) {
        const int tn = t0 + 32 + lane;
        const float xn = (tn < T_STEPS) ? g_r[tn * BATCH + b] : 0.f;

        float y = x, up;
        up = __shfl_up_sync(0xffffffffu, y, 1);  if (lane >= 1)  y = fmaf(l1,  up, y);
        up = __shfl_up_sync(0xffffffffu, y, 2);  if (lane >= 2)  y = fmaf(l2,  up, y);
        up = __shfl_up_sync(0xffffffffu, y, 4);  if (lane >= 4)  y = fmaf(l4,  up, y);
        up = __shfl_up_sync(0xffffffffu, y, 8);  if (lane >= 8)  y = fmaf(l8,  up, y);
        up = __shfl_up_sync(0xffffffffu, y, 16); if (lane >= 16) y = fmaf(l16, up, y);

        const float li = fmaf(lpow, carry, y);
        if (t0 + lane < T_STEPS)
            out[DEC_OFF + (size_t)(t0 + lane) * BATCH + b] = li;
        carry = __shfl_sync(0xffffffffu, li, 31);
        x = xn;
    }
}

// ---------------------------------------------------------------------------
extern "C" void kernel_launch(void* const* d_in, const int* in_sizes, int n_in,
                              void* d_out, int out_size)
{
    const float* x    = (const float*)d_in[0];
    const float* st   = (const float*)d_in[1];
    const float* stLI = (const float*)d_in[2];
    const float* W1   = (const float*)d_in[3];
    const float* W2   = (const float*)d_in[4];
    const float* a_   = (const float*)d_in[5];
    const float* b_   = (const float*)d_in[6];
    const float* c_   = (const float*)d_in[7];
    const float* d_   = (const float*)d_in[8];
    const float* v2_  = (const float*)d_in[9];
    const float* v1_  = (const float*)d_in[10];
    const float* v0_  = (const float*)d_in[11];
    const float* tau_ = (const float*)d_in[12];
    const float* th_  = (const float*)d_in[13];
    const float* lk_  = (const float*)d_in[14];
    const float* ts_  = (const float*)d_in[15];
    float* out = (float*)d_out;

    const int smem_bytes = 2 * STAGEW * (int)sizeof(uint32_t);   // 73728
    cudaFuncSetAttribute(gemm_f16pair_kernel,
                         cudaFuncAttributeMaxDynamicSharedMemorySize, smem_bytes);

    dim3 ggrid(MROWS / 128, NDIM / 128);   // (500, 4)
    gemm_f16pair_kernel<<<ggrid, 256, smem_bytes>>>(x, W1);
    scan_kernel<<<(BATCH * NDIM) / 128, 128>>>(st, a_, b_, c_, d_, v2_, v1_,
                                               v0_, tau_, th_, ts_, out);
    readout_reduce_kernel<<<T_STEPS * BATCH, 128>>>(out, W2);
    li_kernel<<<BATCH, 32>>>(stLI, lk_, out);
}

// round 12
// speedup vs baseline: 1.4850x; 1.1305x over previous
#include <cuda_runtime.h>
#include <cuda_fp16.h>
#include <cstdint>
#include <cstddef>
#include <cmath>

// Problem constants
#define T_STEPS 1000
#define BATCH   64
#define NDIM    512
#define KDIM    512
#define MROWS   (BATCH * T_STEPS)   // 64000

static constexpr size_t PLANE      = (size_t)BATCH * NDIM;          // 32768
static constexpr size_t STATES_OFF = (size_t)T_STEPS * PLANE;       // outputs plane elems
static constexpr size_t DEC_OFF    = STATES_OFF + 3 * STATES_OFF;   // after states [T,3,B,N]

// Scratch
__device__ __align__(16) float g_I[(size_t)MROWS * NDIM];
__device__ float g_r[T_STEPS * BATCH];

// ---------------------------------------------------------------------------
// fp16 Dekker-pair: x -> half2(hi=rn16(x), lo=rn16(x-hi)), interleaved along
// mma-k. pass1 (A x B) = hi*hi + lo*lo; pass2 (swap16(A) x B) = lo*hi + hi*lo.
// Sum = full (hi+lo)(hi+lo) product, ~2^-22 relative error.
// ---------------------------------------------------------------------------
__device__ __forceinline__ uint32_t pack_hilo(float x) {
    __half h = __float2half_rn(x);
    float r = x - __half2float(h);
    __half2 p = __halves2half2(h, __float2half_rn(r));
    return *reinterpret_cast<uint32_t*>(&p);
}

__device__ __forceinline__ void mma_f16(float* c, const uint32_t* a, const uint32_t* b) {
    asm volatile(
        "mma.sync.aligned.m16n8k16.row.col.f32.f16.f16.f32 "
        "{%0,%1,%2,%3}, {%4,%5,%6,%7}, {%8,%9}, {%0,%1,%2,%3};\n"
        : "+f"(c[0]), "+f"(c[1]), "+f"(c[2]), "+f"(c[3])
        : "r"(a[0]), "r"(a[1]), "r"(a[2]), "r"(a[3]), "r"(b[0]), "r"(b[1]));
}

__device__ __forceinline__ void ldsm_x4(uint32_t* r, uint32_t saddr) {
    asm volatile("ldmatrix.sync.aligned.m8n8.x4.shared.b16 {%0,%1,%2,%3}, [%4];"
                 : "=r"(r[0]), "=r"(r[1]), "=r"(r[2]), "=r"(r[3]) : "r"(saddr));
}

// ---------------------------------------------------------------------------
// Kernel 1: I = X @ W1^T (NT GEMM), fp16 Dekker-pair mma, 2 passes.
// R12: CTA tile 128x64, 256 threads (8 warps, 4x2), warp tile 32x32,
// __launch_bounds__(256,2) -> 2 CTAs/SM with NO spills (~100 regs needed).
// smem/stage = (128+64)*36 words = 27KB; 2 stages = 54KB/CTA.
// Grid (8, 500) bn-fastest: the 8 CTAs sharing an X tile run adjacently -> L2.
// ---------------------------------------------------------------------------
#define BKR    32
#define GCHUNK (KDIM / BKR)        // 16
#define WSTR   36                  // uint32 words per row (32 data + 4 pad)
#define TILE_A (128 * WSTR)        // 4608 words
#define TILE_B (64 * WSTR)         // 2304 words
#define STAGEW (TILE_A + TILE_B)   // 6912 words = 27648 B

struct LdgRegs { float4 a[4]; float4 b[2]; };   // 16 A floats + 8 B floats

__device__ __forceinline__ void ldg_chunk(LdgRegs& r, const float* __restrict__ xptr,
                                          const float* __restrict__ wptr, int ck)
{
    const float4* xa = (const float4*)(xptr + ck * BKR);
    const float4* wa = (const float4*)(wptr + ck * BKR);
    #pragma unroll
    for (int j = 0; j < 4; j++) r.a[j] = xa[j];
    r.b[0] = wa[0]; r.b[1] = wa[1];
}

// A loader: row = tid>>1 (0..127), 16-word half-row.  B loader: row = tid>>2
// (0..63), 8-word quarter-row.
__device__ __forceinline__ void sts_chunk(uint32_t* stage, const LdgRegs& r, int tid)
{
    const int arow = tid >> 1, akb = (tid & 1) * 16;
    const int brow = tid >> 2, bkb = (tid & 3) * 8;
    uint32_t* sA = stage + arow * WSTR + akb;
    uint32_t* sB = stage + TILE_A + brow * WSTR + bkb;
    const float* fa = (const float*)r.a;
    const float* fb = (const float*)r.b;
    #pragma unroll
    for (int j = 0; j < 4; j++) {
        uint4 w;
        w.x = pack_hilo(fa[j * 4 + 0]); w.y = pack_hilo(fa[j * 4 + 1]);
        w.z = pack_hilo(fa[j * 4 + 2]); w.w = pack_hilo(fa[j * 4 + 3]);
        ((uint4*)sA)[j] = w;
    }
    #pragma unroll
    for (int j = 0; j < 2; j++) {
        uint4 w;
        w.x = pack_hilo(fb[j * 4 + 0]); w.y = pack_hilo(fb[j * 4 + 1]);
        w.z = pack_hilo(fb[j * 4 + 2]); w.w = pack_hilo(fb[j * 4 + 3]);
        ((uint4*)sB)[j] = w;
    }
}

__device__ __forceinline__ void compute_chunk(uint32_t stage_saddr,
                                              float (&acc)[2][4][4],
                                              uint32_t aOff, uint32_t bOff)
{
    #pragma unroll
    for (int s = 0; s < 4; s++) {
        const uint32_t kByte = (uint32_t)(s * 8) * 4u;
        uint32_t A[2][4];
        ldsm_x4(A[0], stage_saddr + aOff + kByte);                              // mt 0
        ldsm_x4(A[1], stage_saddr + aOff + (uint32_t)(16 * WSTR * 4) + kByte);  // mt 1
        uint32_t Bt[2][4];
        ldsm_x4(Bt[0], stage_saddr + bOff + kByte);                             // nt 0,1
        ldsm_x4(Bt[1], stage_saddr + bOff + (uint32_t)(16 * WSTR * 4) + kByte); // nt 2,3

        // pass 1: hi*hi + lo*lo — distinct accumulators
        #pragma unroll
        for (int mt = 0; mt < 2; mt++)
            #pragma unroll
            for (int nt = 0; nt < 4; nt++)
                mma_f16(acc[mt][nt], A[mt], &Bt[nt >> 1][(nt & 1) * 2]);
        // pass 2: hi*lo + lo*hi — swap A halves (8 PRMT)
        uint32_t As[2][4];
        #pragma unroll
        for (int mt = 0; mt < 2; mt++)
            #pragma unroll
            for (int j = 0; j < 4; j++)
                As[mt][j] = __byte_perm(A[mt][j], 0, 0x1032);
        #pragma unroll
        for (int mt = 0; mt < 2; mt++)
            #pragma unroll
            for (int nt = 0; nt < 4; nt++)
                mma_f16(acc[mt][nt], As[mt], &Bt[nt >> 1][(nt & 1) * 2]);
    }
}

__global__ __launch_bounds__(256, 2) void gemm_f16pair_kernel(const float* __restrict__ X,
                                                              const float* __restrict__ W)
{
    extern __shared__ uint32_t smemw[];      // 2 stages * 6912 words = 54KB
    const int tid  = threadIdx.x;
    const int wid  = tid >> 5;
    const int lane = tid & 31;
    const int wm   = wid & 3;                // 0..3 (M)
    const int wn   = wid >> 2;               // 0..1 (N)
    const int bn   = blockIdx.x * 64;        // bn fastest -> X tile L2 reuse
    const int bm   = blockIdx.y * 128;

    const uint32_t smem_saddr = (uint32_t)__cvta_generic_to_shared(smemw);

    // ldmatrix per-lane offsets (stage-relative, bytes).
    const int lm = lane & 7;
    // A x4: M0=row+0/w0, M1=row+8/w0, M2=row+0/w4, M3=row+8/w4
    const int aRow = wm * 32 + lm + ((lane >> 3) & 1) * 8;
    const int aWrd = ((lane >> 4) & 1) * 4;
    const uint32_t aOff = (uint32_t)(aRow * WSTR + aWrd) * 4u;
    // B x4: M0=row+0/w0, M1=row+0/w4, M2=row+8/w0, M3=row+8/w4
    const int bRow = wn * 32 + lm + ((lane >> 4) & 1) * 8;
    const int bWrd = ((lane >> 3) & 1) * 4;
    const uint32_t bOff = (uint32_t)(TILE_A + bRow * WSTR + bWrd) * 4u;

    // loader pointers
    const float* xptr = X + (size_t)(bm + (tid >> 1)) * KDIM + (tid & 1) * 16;
    const float* wptr = W + (size_t)(bn + (tid >> 2)) * KDIM + (tid & 3) * 8;

    float acc[2][4][4];
    #pragma unroll
    for (int mt = 0; mt < 2; mt++)
        #pragma unroll
        for (int nt = 0; nt < 4; nt++)
            #pragma unroll
            for (int j = 0; j < 4; j++) acc[mt][nt][j] = 0.f;

    {
        LdgRegs r0;
        ldg_chunk(r0, xptr, wptr, 0);
        sts_chunk(smemw, r0, tid);
    }
    __syncthreads();

    #pragma unroll 1
    for (int ck = 0; ck < GCHUNK; ck++) {
        const int cur = ck & 1;
        LdgRegs nr;
        if (ck < GCHUNK - 1) ldg_chunk(nr, xptr, wptr, ck + 1);   // LDGs in flight
        compute_chunk(smem_saddr + (uint32_t)(cur * STAGEW) * 4u, acc, aOff, bOff);
        if (ck < GCHUNK - 1) sts_chunk(smemw + (cur ^ 1) * STAGEW, nr, tid);
        __syncthreads();
    }

    // Epilogue: direct float2 stores to g_I
    #pragma unroll
    for (int mt = 0; mt < 2; mt++) {
        const int r0 = bm + wm * 32 + mt * 16 + (lane >> 2);
        #pragma unroll
        for (int nt = 0; nt < 4; nt++) {
            const int c = bn + wn * 32 + nt * 8 + 2 * (lane & 3);
            *(float2*)(g_I + (size_t)r0 * NDIM + c)       = make_float2(acc[mt][nt][0], acc[mt][nt][1]);
            *(float2*)(g_I + (size_t)(r0 + 8) * NDIM + c) = make_float2(acc[mt][nt][2], acc[mt][nt][3]);
        }
    }
}

// ---------------------------------------------------------------------------
// Kernel 2: per-neuron Izhikevich scan (frozen, R9-exact)
// ---------------------------------------------------------------------------
struct NeuronP { float TS, V2, V1, V0, KA, Bp, TH, Cc, D; };

__device__ __forceinline__ void snn_step(float Ic, int t, int g,
                                         const NeuronP& P, float& u, float& v,
                                         float* __restrict__ out)
{
    float t0 = P.V0 - u + Ic;
    t0 = fmaf(P.V1, v, t0);
    t0 = fmaf(P.V2, v * v, t0);
    const float vn = fmaf(P.TS, t0, v);
    const float un = fmaf(P.KA, fmaf(P.Bp, v, -u), u);
    const bool  sp = (vn - P.TH) > 0.f;
    const float s  = sp ? 1.f : 0.f;
    const float vo = sp ? P.Cc : vn;
    const float uo = sp ? (un + P.D) : un;

    out[(size_t)t * PLANE + g] = s;
    const size_t sb = STATES_OFF + (size_t)t * (3 * PLANE) + g;
    out[sb]             = uo;
    out[sb + PLANE]     = vo;
    out[sb + 2 * PLANE] = s;
    u = uo; v = vo;
}

__global__ __launch_bounds__(128) void scan_kernel(
    const float* __restrict__ st,
    const float* __restrict__ pa,  const float* __restrict__ pb,
    const float* __restrict__ pc,  const float* __restrict__ pd,
    const float* __restrict__ pv2, const float* __restrict__ pv1,
    const float* __restrict__ pv0, const float* __restrict__ ptau,
    const float* __restrict__ pth, const float* __restrict__ pts,
    float* __restrict__ out)
{
    const int g = blockIdx.x * 128 + threadIdx.x;
    const int n = g & (NDIM - 1);

    NeuronP P;
    P.TS = pts[n];
    P.V2 = pv2[n]; P.V1 = pv1[n]; P.V0 = pv0[n];
    P.KA = P.TS / ptau[n] * pa[n];
    P.Bp = pb[n]; P.TH = pth[n]; P.Cc = pc[n]; P.D = pd[n];

    float u = st[g];
    float v = st[PLANE + g];

    const float* Ip = g_I + (size_t)(g >> 9) * ((size_t)T_STEPS * NDIM) + n;

    float bufA[8], bufB[8];
    #pragma unroll
    for (int p = 0; p < 8; p++) bufA[p] = Ip[(size_t)p * NDIM];

    #pragma unroll 1
    for (int t0 = 0; t0 < 992; t0 += 16) {
        #pragma unroll
        for (int p = 0; p < 8; p++) bufB[p] = Ip[(size_t)(t0 + 8 + p) * NDIM];
        #pragma unroll
        for (int p = 0; p < 8; p++) snn_step(bufA[p], t0 + p, g, P, u, v, out);
        #pragma unroll
        for (int p = 0; p < 8; p++) bufA[p] = Ip[(size_t)(t0 + 16 + p) * NDIM];
        #pragma unroll
        for (int p = 0; p < 8; p++) snn_step(bufB[p], t0 + 8 + p, g, P, u, v, out);
    }
    #pragma unroll
    for (int p = 0; p < 8; p++) snn_step(bufA[p], 992 + p, g, P, u, v, out);
}

// ---------------------------------------------------------------------------
// Kernel 3: r[t*B+b] = sum_n s[t,b,n] * W2[n]  (frozen)
// ---------------------------------------------------------------------------
__global__ __launch_bounds__(128) void readout_reduce_kernel(
    const float* __restrict__ out, const float* __restrict__ W2)
{
    const int tb = blockIdx.x;
    const float* sp = out + (size_t)tb * NDIM;
    const int tid = threadIdx.x;

    float sum = 0.f;
    #pragma unroll
    for (int j = 0; j < 4; j++) {
        const int n = tid + j * 128;
        sum = fmaf(sp[n], W2[n], sum);
    }
    #pragma unroll
    for (int o = 16; o > 0; o >>= 1)
        sum += __shfl_xor_sync(0xffffffffu, sum, o);

    __shared__ float ws[4];
    if ((tid & 31) == 0) ws[tid >> 5] = sum;
    __syncthreads();
    if (tid == 0) g_r[tb] = (ws[0] + ws[1]) + (ws[2] + ws[3]);
}

// ---------------------------------------------------------------------------
// Kernel 4: li recurrence — warp-parallel linear-recurrence scan (frozen)
// ---------------------------------------------------------------------------
__global__ void li_kernel(const float* __restrict__ stLI,
                          const float* __restrict__ leak,
                          float* __restrict__ out)
{
    const int b = blockIdx.x;
    const int lane = threadIdx.x;    // 32 threads
    const float lk = leak[0];
    const float l1 = lk, l2 = l1 * l1, l4 = l2 * l2, l8 = l4 * l4, l16 = l8 * l8;
    float lpow = lk;                 // leak^(lane+1)
    {
        float sq[5] = {l1, l2, l4, l8, l16};
        #pragma unroll
        for (int i = 0; i < 5; i++)
            if ((lane >> i) & 1) lpow *= sq[i];
    }

    float carry = stLI[b];
    float x = g_r[lane * BATCH + b];

    #pragma unroll 1
    for (int t0 = 0; t0 < T_STEPS; t0 += 32) {
        const int tn = t0 + 32 + lane;
        const float xn = (tn < T_STEPS) ? g_r[tn * BATCH + b] : 0.f;

        float y = x, up;
        up = __shfl_up_sync(0xffffffffu, y, 1);  if (lane >= 1)  y = fmaf(l1,  up, y);
        up = __shfl_up_sync(0xffffffffu, y, 2);  if (lane >= 2)  y = fmaf(l2,  up, y);
        up = __shfl_up_sync(0xffffffffu, y, 4);  if (lane >= 4)  y = fmaf(l4,  up, y);
        up = __shfl_up_sync(0xffffffffu, y, 8);  if (lane >= 8)  y = fmaf(l8,  up, y);
        up = __shfl_up_sync(0xffffffffu, y, 16); if (lane >= 16) y = fmaf(l16, up, y);

        const float li = fmaf(lpow, carry, y);
        if (t0 + lane < T_STEPS)
            out[DEC_OFF + (size_t)(t0 + lane) * BATCH + b] = li;
        carry = __shfl_sync(0xffffffffu, li, 31);
        x = xn;
    }
}

// ---------------------------------------------------------------------------
extern "C" void kernel_launch(void* const* d_in, const int* in_sizes, int n_in,
                              void* d_out, int out_size)
{
    const float* x    = (const float*)d_in[0];
    const float* st   = (const float*)d_in[1];
    const float* stLI = (const float*)d_in[2];
    const float* W1   = (const float*)d_in[3];
    const float* W2   = (const float*)d_in[4];
    const float* a_   = (const float*)d_in[5];
    const float* b_   = (const float*)d_in[6];
    const float* c_   = (const float*)d_in[7];
    const float* d_   = (const float*)d_in[8];
    const float* v2_  = (const float*)d_in[9];
    const float* v1_  = (const float*)d_in[10];
    const float* v0_  = (const float*)d_in[11];
    const float* tau_ = (const float*)d_in[12];
    const float* th_  = (const float*)d_in[13];
    const float* lk_  = (const float*)d_in[14];
    const float* ts_  = (const float*)d_in[15];
    float* out = (float*)d_out;

    const int smem_bytes = 2 * STAGEW * (int)sizeof(uint32_t);   // 55296
    cudaFuncSetAttribute(gemm_f16pair_kernel,
                         cudaFuncAttributeMaxDynamicSharedMemorySize, smem_bytes);

    dim3 ggrid(NDIM / 64, MROWS / 128);   // (8, 500): bn fastest for X L2 reuse
    gemm_f16pair_kernel<<<ggrid, 256, smem_bytes>>>(x, W1);
    scan_kernel<<<(BATCH * NDIM) / 128, 128>>>(st, a_, b_, c_, d_, v2_, v1_,
                                               v0_, tau_, th_, ts_, out);
    readout_reduce_kernel<<<T_STEPS * BATCH, 128>>>(out, W2);
    li_kernel<<<BATCH, 32>>>(stLI, lk_, out);
}

// round 14
// speedup vs baseline: 1.5636x; 1.0529x over previous
#include <cuda_runtime.h>
#include <cuda_fp16.h>
#include <cstdint>
#include <cstddef>
#include <cmath>

// Problem constants
#define T_STEPS 1000
#define BATCH   64
#define NDIM    512
#define KDIM    512
#define MROWS   (BATCH * T_STEPS)   // 64000

#define NT_CHUNKS 4
#define T_CHK     (T_STEPS / NT_CHUNKS)        // 250 t-steps per chunk
#define ROWS_CHK  (T_CHK * BATCH)              // 16000 m-rows per chunk

static constexpr size_t PLANE      = (size_t)BATCH * NDIM;          // 32768
static constexpr size_t STATES_OFF = (size_t)T_STEPS * PLANE;       // outputs plane elems
static constexpr size_t DEC_OFF    = STATES_OFF + 3 * STATES_OFF;   // after states [T,3,B,N]

// Scratch. g_I is [t, b, n]-major: row m = t*BATCH + b.
__device__ __align__(16) float g_I[(size_t)MROWS * NDIM];
__device__ float g_r[T_STEPS * BATCH];
__device__ float g_u[PLANE];     // carried scan state between t-chunks
__device__ float g_v[PLANE];

// ---------------------------------------------------------------------------
// fp16 Dekker-pair: x -> half2(hi=rn16(x), lo=rn16(x-hi)), interleaved along
// mma-k. pass1 (A x B) = hi*hi + lo*lo; pass2 (swap16(A) x B) = hi*lo + lo*hi.
// Sum = full (hi+lo)(hi+lo) product, ~2^-22 relative error.
// ---------------------------------------------------------------------------
__device__ __forceinline__ uint32_t pack_hilo(float x) {
    __half h = __float2half_rn(x);
    float r = x - __half2float(h);
    __half2 p = __halves2half2(h, __float2half_rn(r));
    return *reinterpret_cast<uint32_t*>(&p);
}

__device__ __forceinline__ void mma_f16(float* c, const uint32_t* a, const uint32_t* b) {
    asm volatile(
        "mma.sync.aligned.m16n8k16.row.col.f32.f16.f16.f32 "
        "{%0,%1,%2,%3}, {%4,%5,%6,%7}, {%8,%9}, {%0,%1,%2,%3};\n"
        : "+f"(c[0]), "+f"(c[1]), "+f"(c[2]), "+f"(c[3])
        : "r"(a[0]), "r"(a[1]), "r"(a[2]), "r"(a[3]), "r"(b[0]), "r"(b[1]));
}

__device__ __forceinline__ void ldsm_x4(uint32_t* r, uint32_t saddr) {
    asm volatile("ldmatrix.sync.aligned.m8n8.x4.shared.b16 {%0,%1,%2,%3}, [%4];"
                 : "=r"(r[0]), "=r"(r[1]), "=r"(r[2]), "=r"(r[3]) : "r"(saddr));
}

// ---------------------------------------------------------------------------
// Kernel 1: I[m,:] = X[perm(m),:] @ W1^T — R9-exact core, m = t*BATCH + b,
// X row index = b*T_STEPS + t. 512 threads, 16 warps 4x4, warp tile 32x32,
// ldmatrix fragment loads, register-staged double buffer, stride-36 smem.
// ---------------------------------------------------------------------------
#define BKR    32
#define GCHUNK (KDIM / BKR)        // 16
#define WSTR   36
#define TILEW  (128 * WSTR)
#define STAGEW (2 * TILEW)

struct LdgRegs { float4 a[2]; float4 b[2]; };

__device__ __forceinline__ void ldg_chunk(LdgRegs& r, const float* __restrict__ xptr,
                                          const float* __restrict__ wptr, int ck)
{
    const float4* xa = (const float4*)(xptr + ck * BKR);
    const float4* wa = (const float4*)(wptr + ck * BKR);
    r.a[0] = xa[0]; r.a[1] = xa[1];
    r.b[0] = wa[0]; r.b[1] = wa[1];
}

__device__ __forceinline__ void sts_chunk(uint32_t* stage, const LdgRegs& r, int row, int kb)
{
    uint32_t* sA = stage + row * WSTR + kb;
    uint32_t* sB = sA + TILEW;
    const float* fa = (const float*)r.a;
    const float* fb = (const float*)r.b;
    #pragma unroll
    for (int j = 0; j < 2; j++) {
        uint4 w;
        w.x = pack_hilo(fa[j * 4 + 0]); w.y = pack_hilo(fa[j * 4 + 1]);
        w.z = pack_hilo(fa[j * 4 + 2]); w.w = pack_hilo(fa[j * 4 + 3]);
        ((uint4*)sA)[j] = w;
    }
    #pragma unroll
    for (int j = 0; j < 2; j++) {
        uint4 w;
        w.x = pack_hilo(fb[j * 4 + 0]); w.y = pack_hilo(fb[j * 4 + 1]);
        w.z = pack_hilo(fb[j * 4 + 2]); w.w = pack_hilo(fb[j * 4 + 3]);
        ((uint4*)sB)[j] = w;
    }
}

__device__ __forceinline__ void compute_chunk(uint32_t stage_saddr,
                                              float (&acc)[2][4][4],
                                              uint32_t aOff, uint32_t bOff)
{
    #pragma unroll
    for (int s = 0; s < 4; s++) {
        const uint32_t kByte = (uint32_t)(s * 8) * 4u;
        uint32_t A[2][4];
        ldsm_x4(A[0], stage_saddr + aOff + kByte);
        ldsm_x4(A[1], stage_saddr + aOff + (uint32_t)(16 * WSTR * 4) + kByte);
        uint32_t Bt[2][4];
        ldsm_x4(Bt[0], stage_saddr + bOff + kByte);
        ldsm_x4(Bt[1], stage_saddr + bOff + (uint32_t)(16 * WSTR * 4) + kByte);

        #pragma unroll
        for (int mt = 0; mt < 2; mt++)
            #pragma unroll
            for (int nt = 0; nt < 4; nt++)
                mma_f16(acc[mt][nt], A[mt], &Bt[nt >> 1][(nt & 1) * 2]);
        uint32_t As[2][4];
        #pragma unroll
        for (int mt = 0; mt < 2; mt++)
            #pragma unroll
            for (int j = 0; j < 4; j++)
                As[mt][j] = __byte_perm(A[mt][j], 0, 0x1032);
        #pragma unroll
        for (int mt = 0; mt < 2; mt++)
            #pragma unroll
            for (int nt = 0; nt < 4; nt++)
                mma_f16(acc[mt][nt], As[mt], &Bt[nt >> 1][(nt & 1) * 2]);
    }
}

__global__ __launch_bounds__(512, 1) void gemm_f16pair_kernel(const float* __restrict__ X,
                                                              const float* __restrict__ W,
                                                              int bm_base)
{
    extern __shared__ uint32_t smemw[];      // 72KB
    const int tid  = threadIdx.x;
    const int wid  = tid >> 5;
    const int lane = tid & 31;
    const int wm   = wid & 3;
    const int wn   = wid >> 2;
    const int bm   = bm_base + blockIdx.x * 128;
    const int bn   = blockIdx.y * 128;

    const uint32_t smem_saddr = (uint32_t)__cvta_generic_to_shared(smemw);

    const int lm = lane & 7;
    const int aRow = wm * 32 + lm + ((lane >> 3) & 1) * 8;
    const int aWrd = ((lane >> 4) & 1) * 4;
    const uint32_t aOff = (uint32_t)(aRow * WSTR + aWrd) * 4u;
    const int bRow = wn * 32 + lm + ((lane >> 4) & 1) * 8;
    const int bWrd = ((lane >> 3) & 1) * 4;
    const uint32_t bOff = (uint32_t)(TILEW + bRow * WSTR + bWrd) * 4u;

    // loader: m-row = bm + (tid>>2); X row = b*T_STEPS + t for m = t*BATCH + b
    const int lrow = tid >> 2;
    const int lkb  = (tid & 3) * 8;
    const int mrow = bm + lrow;
    const int xrow = (mrow & (BATCH - 1)) * T_STEPS + (mrow / BATCH);
    const float* xptr = X + (size_t)xrow * KDIM + lkb;
    const float* wptr = W + (size_t)(bn + lrow) * KDIM + lkb;

    float acc[2][4][4];
    #pragma unroll
    for (int mt = 0; mt < 2; mt++)
        #pragma unroll
        for (int nt = 0; nt < 4; nt++)
            #pragma unroll
            for (int j = 0; j < 4; j++) acc[mt][nt][j] = 0.f;

    {
        LdgRegs r0;
        ldg_chunk(r0, xptr, wptr, 0);
        sts_chunk(smemw, r0, lrow, lkb);
    }
    __syncthreads();

    #pragma unroll 1
    for (int ck = 0; ck < GCHUNK; ck++) {
        const int cur = ck & 1;
        LdgRegs nr;
        if (ck < GCHUNK - 1) ldg_chunk(nr, xptr, wptr, ck + 1);
        compute_chunk(smem_saddr + (uint32_t)(cur * STAGEW) * 4u, acc, aOff, bOff);
        if (ck < GCHUNK - 1) sts_chunk(smemw + (cur ^ 1) * STAGEW, nr, lrow, lkb);
        __syncthreads();
    }

    #pragma unroll
    for (int mt = 0; mt < 2; mt++) {
        const int r0 = bm + wm * 32 + mt * 16 + (lane >> 2);
        #pragma unroll
        for (int nt = 0; nt < 4; nt++) {
            const int c = bn + wn * 32 + nt * 8 + 2 * (lane & 3);
            *(float2*)(g_I + (size_t)r0 * NDIM + c)       = make_float2(acc[mt][nt][0], acc[mt][nt][1]);
            *(float2*)(g_I + (size_t)(r0 + 8) * NDIM + c) = make_float2(acc[mt][nt][2], acc[mt][nt][3]);
        }
    }
}

// ---------------------------------------------------------------------------
// Kernel 2: Izhikevich scan over one t-chunk [tbase, tbase+T_CHK).
// I is [t,b,n]: thread g reads g_I[t*PLANE + g] — fully coalesced per warp.
// (u,v) carried via g_u/g_v between chunks (chunk 0 reads state_snn).
// ---------------------------------------------------------------------------
struct NeuronP { float TS, V2, V1, V0, KA, Bp, TH, Cc, D; };

__device__ __forceinline__ void snn_step(float Ic, int t, int g,
                                         const NeuronP& P, float& u, float& v,
                                         float* __restrict__ out)
{
    float t0 = P.V0 - u + Ic;
    t0 = fmaf(P.V1, v, t0);
    t0 = fmaf(P.V2, v * v, t0);
    const float vn = fmaf(P.TS, t0, v);
    const float un = fmaf(P.KA, fmaf(P.Bp, v, -u), u);
    const bool  sp = (vn - P.TH) > 0.f;
    const float s  = sp ? 1.f : 0.f;
    const float vo = sp ? P.Cc : vn;
    const float uo = sp ? (un + P.D) : un;

    out[(size_t)t * PLANE + g] = s;
    const size_t sb = STATES_OFF + (size_t)t * (3 * PLANE) + g;
    out[sb]             = uo;
    out[sb + PLANE]     = vo;
    out[sb + 2 * PLANE] = s;
    u = uo; v = vo;
}

__global__ __launch_bounds__(128) void scan_kernel(
    const float* __restrict__ st,
    const float* __restrict__ pa,  const float* __restrict__ pb,
    const float* __restrict__ pc,  const float* __restrict__ pd,
    const float* __restrict__ pv2, const float* __restrict__ pv1,
    const float* __restrict__ pv0, const float* __restrict__ ptau,
    const float* __restrict__ pth, const float* __restrict__ pts,
    float* __restrict__ out, int tbase)
{
    const int g = blockIdx.x * 128 + threadIdx.x;
    const int n = g & (NDIM - 1);

    NeuronP P;
    P.TS = pts[n];
    P.V2 = pv2[n]; P.V1 = pv1[n]; P.V0 = pv0[n];
    P.KA = P.TS / ptau[n] * pa[n];
    P.Bp = pb[n]; P.TH = pth[n]; P.Cc = pc[n]; P.D = pd[n];

    float u, v;
    if (tbase == 0) { u = st[g]; v = st[PLANE + g]; }
    else            { u = g_u[g]; v = g_v[g]; }

    const float* Ip = g_I + (size_t)tbase * PLANE + g;   // step stride = PLANE

    float bufA[8], bufB[8];
    #pragma unroll
    for (int p = 0; p < 8; p++) bufA[p] = __ldcs(Ip + (size_t)p * PLANE);

    // Main loop covers steps [0, 240); after it, bufA holds steps 240..247
    // and Ip sits at base + 240*PLANE.
    #pragma unroll 1
    for (int t0 = 0; t0 < T_CHK - 10; t0 += 16) {
        #pragma unroll
        for (int p = 0; p < 8; p++) bufB[p] = __ldcs(Ip + (size_t)(8 + p) * PLANE);
        #pragma unroll
        for (int p = 0; p < 8; p++) snn_step(bufA[p], tbase + t0 + p, g, P, u, v, out);
        #pragma unroll
        for (int p = 0; p < 8; p++) bufA[p] = __ldcs(Ip + (size_t)(16 + p) * PLANE);
        #pragma unroll
        for (int p = 0; p < 8; p++) snn_step(bufB[p], tbase + t0 + 8 + p, g, P, u, v, out);
        Ip += 16 * PLANE;
    }
    // Tail: steps 240..247 from bufA, then 248..249 at Ip + (8+p)*PLANE.
    #pragma unroll
    for (int p = 0; p < 8; p++) snn_step(bufA[p], tbase + T_CHK - 10 + p, g, P, u, v, out);
    #pragma unroll
    for (int p = 0; p < 2; p++)
        snn_step(__ldcs(Ip + (size_t)(8 + p) * PLANE), tbase + T_CHK - 2 + p, g, P, u, v, out);

    g_u[g] = u;
    g_v[g] = v;
}

// ---------------------------------------------------------------------------
// Kernel 3: r[t*B+b] = sum_n s[t,b,n]*W2[n], chunked by t (tb_base offset)
// ---------------------------------------------------------------------------
__global__ __launch_bounds__(128) void readout_reduce_kernel(
    const float* __restrict__ out, const float* __restrict__ W2, int tb_base)
{
    const int tb = tb_base + blockIdx.x;
    const float* sp = out + (size_t)tb * NDIM;
    const int tid = threadIdx.x;

    float sum = 0.f;
    #pragma unroll
    for (int j = 0; j < 4; j++) {
        const int n = tid + j * 128;
        sum = fmaf(sp[n], W2[n], sum);
    }
    #pragma unroll
    for (int o = 16; o > 0; o >>= 1)
        sum += __shfl_xor_sync(0xffffffffu, sum, o);

    __shared__ float ws[4];
    if ((tid & 31) == 0) ws[tid >> 5] = sum;
    __syncthreads();
    if (tid == 0) g_r[tb] = (ws[0] + ws[1]) + (ws[2] + ws[3]);
}

// ---------------------------------------------------------------------------
// Kernel 4: li recurrence — warp-parallel linear-recurrence scan (frozen)
// ---------------------------------------------------------------------------
__global__ void li_kernel(const float* __restrict__ stLI,
                          const float* __restrict__ leak,
                          float* __restrict__ out)
{
    const int b = blockIdx.x;
    const int lane = threadIdx.x;
    const float lk = leak[0];
    const float l1 = lk, l2 = l1 * l1, l4 = l2 * l2, l8 = l4 * l4, l16 = l8 * l8;
    float lpow = lk;
    {
        float sq[5] = {l1, l2, l4, l8, l16};
        #pragma unroll
        for (int i = 0; i < 5; i++)
            if ((lane >> i) & 1) lpow *= sq[i];
    }

    float carry = stLI[b];
    float x = g_r[lane * BATCH + b];

    #pragma unroll 1
    for (int t0 = 0; t0 < T_STEPS; t0 += 32) {
        const int tn = t0 + 32 + lane;
        const float xn = (tn < T_STEPS) ? g_r[tn * BATCH + b] : 0.f;

        float y = x, up;
        up = __shfl_up_sync(0xffffffffu, y, 1);  if (lane >= 1)  y = fmaf(l1,  up, y);
        up = __shfl_up_sync(0xffffffffu, y, 2);  if (lane >= 2)  y = fmaf(l2,  up, y);
        up = __shfl_up_sync(0xffffffffu, y, 4);  if (lane >= 4)  y = fmaf(l4,  up, y);
        up = __shfl_up_sync(0xffffffffu, y, 8);  if (lane >= 8)  y = fmaf(l8,  up, y);
        up = __shfl_up_sync(0xffffffffu, y, 16); if (lane >= 16) y = fmaf(l16, up, y);

        const float li = fmaf(lpow, carry, y);
        if (t0 + lane < T_STEPS)
            out[DEC_OFF + (size_t)(t0 + lane) * BATCH + b] = li;
        carry = __shfl_sync(0xffffffffu, li, 31);
        x = xn;
    }
}

// ---------------------------------------------------------------------------
extern "C" void kernel_launch(void* const* d_in, const int* in_sizes, int n_in,
                              void* d_out, int out_size)
{
    const float* x    = (const float*)d_in[0];
    const float* st   = (const float*)d_in[1];
    const float* stLI = (const float*)d_in[2];
    const float* W1   = (const float*)d_in[3];
    const float* W2   = (const float*)d_in[4];
    const float* a_   = (const float*)d_in[5];
    const float* b_   = (const float*)d_in[6];
    const float* c_   = (const float*)d_in[7];
    const float* d_   = (const float*)d_in[8];
    const float* v2_  = (const float*)d_in[9];
    const float* v1_  = (const float*)d_in[10];
    const float* v0_  = (const float*)d_in[11];
    const float* tau_ = (const float*)d_in[12];
    const float* th_  = (const float*)d_in[13];
    const float* lk_  = (const float*)d_in[14];
    const float* ts_  = (const float*)d_in[15];
    float* out = (float*)d_out;

    // One-time side stream + events (R10-proven capture pattern).
    static cudaStream_t s_side = nullptr;
    static cudaEvent_t  s_evG[NT_CHUNKS];
    static cudaEvent_t  s_evJoin = nullptr;
    if (!s_side) {
        cudaStreamCreateWithFlags(&s_side, cudaStreamNonBlocking);
        for (int i = 0; i < NT_CHUNKS; i++)
            cudaEventCreateWithFlags(&s_evG[i], cudaEventDisableTiming);
        cudaEventCreateWithFlags(&s_evJoin, cudaEventDisableTiming);
    }

    const int smem_bytes = 2 * STAGEW * (int)sizeof(uint32_t);   // 73728
    cudaFuncSetAttribute(gemm_f16pair_kernel,
                         cudaFuncAttributeMaxDynamicSharedMemorySize, smem_bytes);

    // Stream 0: GEMM t-chunks (250 t x 64 b = 16000 m-rows each).
    dim3 ggrid(ROWS_CHK / 128, NDIM / 128);   // (125, 4)
    for (int c = 0; c < NT_CHUNKS; c++) {
        gemm_f16pair_kernel<<<ggrid, 512, smem_bytes>>>(x, W1, c * ROWS_CHK);
        cudaEventRecord(s_evG[c], 0);
    }

    // Side stream: scan+reduce for t-chunk c as soon as its GEMM is done —
    // overlaps GEMM chunk c+1. Scan chunks chain on g_u/g_v in-stream.
    for (int c = 0; c < NT_CHUNKS; c++) {
        cudaStreamWaitEvent(s_side, s_evG[c], 0);
        scan_kernel<<<(int)(PLANE / 128), 128, 0, s_side>>>(
            st, a_, b_, c_, d_, v2_, v1_, v0_, tau_, th_, ts_, out, c * T_CHK);
        readout_reduce_kernel<<<T_CHK * BATCH, 128, 0, s_side>>>(
            out, W2, c * T_CHK * BATCH);
    }

    // Join, then li.
    cudaEventRecord(s_evJoin, s_side);
    cudaStreamWaitEvent(0, s_evJoin, 0);
    li_kernel<<<BATCH, 32>>>(stLI, lk_, out);
}